// round 16
// baseline (speedup 1.0000x reference)
#include <cuda_runtime.h>
#include <cuda_bf16.h>

#define DD  512    // model dim
#define EE  32     // experts
#define HH  512    // hidden per gate branch
#define LL  512    // tokens
#define TPB 256

// ---------------- scratch (static device globals; no allocs) ----------------
__device__ int            g_cnt[EE];
__device__ int            g_tok[EE][LL];
__device__ float          g_wt [EE][LL];
__device__ unsigned char  g_kis[EE][LL];
__device__ __align__(16) float g_actT[EE][HH][LL];   // [expert][h][token-slot]
__device__ __align__(16) float g_buf[2][LL * DD];

// ---------------- helpers ----------------
__device__ __forceinline__ float warp_sum(float s) {
    #pragma unroll
    for (int o = 16; o; o >>= 1) s += __shfl_xor_sync(0xffffffffu, s, o);
    return s;
}
__device__ __forceinline__ float gelu_tanh(float g) {
    float inner = 0.7978845608028654f * (g + 0.044715f * g * g * g);
    return 0.5f * g * (1.f + tanhf(inner));
}
// acc (f4 over 4 tokens) += sum over 4 k of xv[k] * g.component(k)
__device__ __forceinline__ void fma_tok4_k4(float4& a, const float4* xv, float4 g) {
    a.x = fmaf(xv[0].x, g.x, a.x); a.x = fmaf(xv[1].x, g.y, a.x);
    a.x = fmaf(xv[2].x, g.z, a.x); a.x = fmaf(xv[3].x, g.w, a.x);
    a.y = fmaf(xv[0].y, g.x, a.y); a.y = fmaf(xv[1].y, g.y, a.y);
    a.y = fmaf(xv[2].y, g.z, a.y); a.y = fmaf(xv[3].y, g.w, a.y);
    a.z = fmaf(xv[0].z, g.x, a.z); a.z = fmaf(xv[1].z, g.y, a.z);
    a.z = fmaf(xv[2].z, g.z, a.z); a.z = fmaf(xv[3].z, g.w, a.z);
    a.w = fmaf(xv[0].w, g.x, a.w); a.w = fmaf(xv[1].w, g.y, a.w);
    a.w = fmaf(xv[2].w, g.z, a.w); a.w = fmaf(xv[3].w, g.w, a.w);
}
__device__ __forceinline__ void fma_tok4_s(float4& a, float4 xv, float s) {
    a.x = fmaf(xv.x, s, a.x); a.y = fmaf(xv.y, s, a.y);
    a.z = fmaf(xv.z, s, a.z); a.w = fmaf(xv.w, s, a.w);
}

// ---------------- K0 ----------------
__global__ void k0_zero() {
    if (threadIdx.x < EE) g_cnt[threadIdx.x] = 0;
}

// ---------------- K1: routing ----------------
__global__ __launch_bounds__(TPB) void k1_router(
    const float* __restrict__ x, const float* __restrict__ router_scale,
    const float* __restrict__ Wr, const float* __restrict__ escale)
{
    const int tok = blockIdx.x, t = threadIdx.x, lane = t & 31, wid = t >> 5;

    __shared__ float srin[DD];
    __shared__ float spart[8][EE];
    __shared__ float sred[8];

    const float* xrow = x + (size_t)tok * DD;
    float v0 = xrow[t], v1 = xrow[t + TPB];
    float ss = warp_sum(v0 * v0 + v1 * v1);
    if (lane == 0) sred[wid] = ss;
    __syncthreads();
    if (t == 0) {
        float tot = 0.f;
        #pragma unroll
        for (int i = 0; i < 8; i++) tot += sred[i];
        sred[0] = rsqrtf(tot / (float)DD + 1e-6f) * rsqrtf((float)DD);
    }
    __syncthreads();
    const float scl = sred[0];
    srin[t]       = v0 * scl * router_scale[t];
    srin[t + TPB] = v1 * scl * router_scale[t + TPB];
    __syncthreads();

    {
        float acc = 0.f;
        const int d0 = wid * 64;
        #pragma unroll 8
        for (int i = 0; i < 64; i++)
            acc = fmaf(srin[d0 + i], Wr[(d0 + i) * EE + lane], acc);
        spart[wid][lane] = acc;
    }
    __syncthreads();

    if (wid == 0) {
        float l = 0.f;
        #pragma unroll
        for (int i = 0; i < 8; i++) l += spart[i][lane];

        float m1 = l; int i1 = lane;
        #pragma unroll
        for (int o = 16; o; o >>= 1) {
            float om = __shfl_xor_sync(0xffffffffu, m1, o);
            int   oi = __shfl_xor_sync(0xffffffffu, i1, o);
            if (om > m1 || (om == m1 && oi < i1)) { m1 = om; i1 = oi; }
        }
        float l2 = (lane == i1) ? -3.4e38f : l;
        float m2 = l2; int i2 = lane;
        #pragma unroll
        for (int o = 16; o; o >>= 1) {
            float om = __shfl_xor_sync(0xffffffffu, m2, o);
            int   oi = __shfl_xor_sync(0xffffffffu, i2, o);
            if (om > m2 || (om == m2 && oi < i2)) { m2 = om; i2 = oi; }
        }
        if (lane == 0) {
            float p2  = expf(m2 - m1);
            float inv = 1.f / (1.f + p2);
            float w1  = inv      * escale[i1];
            float w2  = p2 * inv * escale[i2];
            int p;
            p = atomicAdd(&g_cnt[i1], 1);
            g_tok[i1][p] = tok; g_wt[i1][p] = w1; g_kis[i1][p] = 0;
            p = atomicAdd(&g_cnt[i2], 1);
            g_tok[i2][p] = tok; g_wt[i2][p] = w2; g_kis[i2][p] = 1;
        }
    }
}

// ---------------- K2a: gate GEMM + GeGLU ----------------
// grid = e(32) x hc(8) x tile(32 of 16 tokens); 128 threads
// thread: 4 tokens (f4) x 2 h x 2 branches; k-blocked by 4
__global__ __launch_bounds__(128) void k2a_gate(
    const float* __restrict__ x, const float* __restrict__ Gate)
{
    const int b    = blockIdx.x;
    const int tile = b & 31;
    const int hc   = (b >> 5) & 7;
    const int e    = b >> 8;

    const int n  = g_cnt[e];
    const int t0 = tile * 16;
    if (t0 >= n) return;
    const int nt = min(16, n - t0);

    __shared__ __align__(16) float sXT[64][20];   // [k][token], 16 tok + pad
    __shared__ __align__(16) float sG[128][68];   // [grow][k]
    __shared__ int   stok[16];
    __shared__ float swgt[16];

    const int tid = threadIdx.x;
    if (tid < 16) {
        const bool v = (tid < nt);
        stok[tid] = v ? g_tok[e][t0 + tid] : -1;
        swgt[tid] = v ? g_wt[e][t0 + tid]  : 0.f;
    }
    __syncthreads();

    const int tt = tid & 3;     // token group: tokens tt*4 .. +3
    const int rr = tid >> 2;    // h group: h = h0 + rr*2, rr*2+1 (both branches)
    const int h0 = hc * 64;
    const float* Gexp = Gate + (size_t)e * 2 * HH * DD;

    float4 acc0[2], acc1[2];
    #pragma unroll
    for (int j = 0; j < 2; j++) {
        acc0[j] = make_float4(0.f, 0.f, 0.f, 0.f);
        acc1[j] = make_float4(0.f, 0.f, 0.f, 0.f);
    }

    for (int c = 0; c < 8; c++) {          // k-chunks of 64
        // stage X transposed: 16 tok x 64 k (256 f4, 2/thread)
        #pragma unroll
        for (int r = 0; r < 2; r++) {
            int f = tid + r * 128, row = f >> 4, col4 = f & 15;
            int tk = stok[row];
            float4 v = make_float4(0.f, 0.f, 0.f, 0.f);
            if (tk >= 0)
                v = *(const float4*)(x + (size_t)tk * DD + c * 64 + col4 * 4);
            sXT[col4 * 4 + 0][row] = v.x;
            sXT[col4 * 4 + 1][row] = v.y;
            sXT[col4 * 4 + 2][row] = v.z;
            sXT[col4 * 4 + 3][row] = v.w;
        }
        // stage G: rows 0..63 = branch0 h0.., 64..127 = branch1 (2048 f4, 16/thread)
        #pragma unroll
        for (int r = 0; r < 16; r++) {
            int f = tid + r * 128, row = f >> 4, col4 = f & 15;
            int grow = (row < 64) ? (h0 + row) : (HH + h0 + row - 64);
            *(float4*)&sG[row][col4 * 4] =
                *(const float4*)(Gexp + (size_t)grow * DD + c * 64 + col4 * 4);
        }
        __syncthreads();

        #pragma unroll 4
        for (int kb = 0; kb < 16; kb++) {   // 4 k per iteration
            float4 xv[4];
            #pragma unroll
            for (int u = 0; u < 4; u++)
                xv[u] = *(const float4*)&sXT[kb * 4 + u][tt * 4];
            float4 g0[2], g1[2];
            #pragma unroll
            for (int j = 0; j < 2; j++) {
                g0[j] = *(const float4*)&sG[rr * 2 + j][kb * 4];
                g1[j] = *(const float4*)&sG[64 + rr * 2 + j][kb * 4];
            }
            #pragma unroll
            for (int j = 0; j < 2; j++) {
                fma_tok4_k4(acc0[j], xv, g0[j]);
                fma_tok4_k4(acc1[j], xv, g1[j]);
            }
        }
        __syncthreads();
    }

    // epilogue: GeGLU * weight (padded slots -> 0), token-contiguous f4 store
    #pragma unroll
    for (int j = 0; j < 2; j++) {
        const int h = h0 + rr * 2 + j;
        float4 a0 = acc0[j], a1 = acc1[j], o;
        o.x = gelu_tanh(a0.x) * a1.x * swgt[tt * 4 + 0];
        o.y = gelu_tanh(a0.y) * a1.y * swgt[tt * 4 + 1];
        o.z = gelu_tanh(a0.z) * a1.z * swgt[tt * 4 + 2];
        o.w = gelu_tanh(a0.w) * a1.w * swgt[tt * 4 + 3];
        *(float4*)&g_actT[e][h][t0 + tt * 4] = o;
    }
}

// ---------------- K2b: down-projection GEMM ----------------
// grid = e(32) x dc(8 of 64 d) x tile(32 of 16 tokens); 128 threads
// thread: 4 tokens (f4) x 2 d; h-blocked by 4
__global__ __launch_bounds__(128) void k2b_down(
    const float* __restrict__ Lin)
{
    const int b    = blockIdx.x;
    const int tile = b & 31;
    const int dc   = (b >> 5) & 7;
    const int e    = b >> 8;

    const int n  = g_cnt[e];
    const int t0 = tile * 16;
    if (t0 >= n) return;
    const int nt = min(16, n - t0);

    __shared__ __align__(16) float sA[64][20];    // [h][token]
    __shared__ __align__(16) float sL[64][68];    // [h][d] (64 d + pad)
    __shared__ int   stok[16];
    __shared__ unsigned char skis[16];

    const int tid = threadIdx.x;
    if (tid < 16) {
        const bool v = (tid < nt);
        stok[tid] = v ? g_tok[e][t0 + tid] : -1;
        skis[tid] = v ? g_kis[e][t0 + tid] : 0;
    }
    __syncthreads();

    const int tt = tid & 3;     // token group
    const int dd = tid >> 2;    // d = dc*64 + dd*2, +1
    const float* Lexp = Lin + (size_t)e * HH * DD;

    float4 acc[2];
    acc[0] = make_float4(0.f, 0.f, 0.f, 0.f);
    acc[1] = make_float4(0.f, 0.f, 0.f, 0.f);

    for (int c = 0; c < 8; c++) {          // h-chunks of 64
        // stage A: 64 h x 16 tok (256 f4, 2/thread) — already transposed in gmem
        #pragma unroll
        for (int r = 0; r < 2; r++) {
            int f = tid + r * 128, row = f >> 2, col4 = f & 3;
            *(float4*)&sA[row][col4 * 4] =
                *(const float4*)&g_actT[e][c * 64 + row][t0 + col4 * 4];
        }
        // stage Lin: 64 h x 64 d (1024 f4, 8/thread)
        #pragma unroll
        for (int r = 0; r < 8; r++) {
            int f = tid + r * 128, row = f >> 4, col4 = f & 15;
            *(float4*)&sL[row][col4 * 4] =
                *(const float4*)(Lexp + (size_t)(c * 64 + row) * DD + dc * 64 + col4 * 4);
        }
        __syncthreads();

        #pragma unroll 4
        for (int hb = 0; hb < 16; hb++) {   // 4 h per iteration
            #pragma unroll
            for (int u = 0; u < 4; u++) {
                float4 xv = *(const float4*)&sA[hb * 4 + u][tt * 4];
                float2 lv = *(const float2*)&sL[hb * 4 + u][dd * 2];
                fma_tok4_s(acc[0], xv, lv.x);
                fma_tok4_s(acc[1], xv, lv.y);
            }
        }
        __syncthreads();
    }

    // epilogue: per-token float2 stores
    const int d0 = dc * 64 + dd * 2;
    const float* a0 = (const float*)&acc[0];
    const float* a1 = (const float*)&acc[1];
    #pragma unroll
    for (int cc = 0; cc < 4; cc++) {
        const int li = tt * 4 + cc;
        if (li < nt) {
            const int tok = stok[li];
            const int ki  = skis[li];
            float2 w = make_float2(a0[cc], a1[cc]);
            *(float2*)&g_buf[ki][(size_t)tok * DD + d0] = w;
        }
    }
}

// ---------------- K3: combine ----------------
__global__ void k3_sum(float* __restrict__ out) {
    const int i = blockIdx.x * blockDim.x + threadIdx.x;
    float4 a = ((const float4*)g_buf[0])[i];
    float4 b = ((const float4*)g_buf[1])[i];
    ((float4*)out)[i] = make_float4(a.x + b.x, a.y + b.y, a.z + b.z, a.w + b.w);
}

// ---------------- dispatch ----------------
extern "C" void kernel_launch(void* const* d_in, const int* in_sizes, int n_in,
                              void* d_out, int out_size) {
    const float *x, *rscale, *Wr, *Gate, *Lin, *escale;
    if (n_in == 6) {
        int ord[6] = {0, 1, 2, 3, 4, 5};
        for (int i = 1; i < 6; i++) {
            int v = ord[i], j = i - 1;
            while (j >= 0 && in_sizes[ord[j]] > in_sizes[v]) { ord[j + 1] = ord[j]; j--; }
            ord[j + 1] = v;
        }
        escale = (const float*)d_in[ord[0]];
        rscale = (const float*)d_in[ord[1]];
        Wr     = (const float*)d_in[ord[2]];
        x      = (const float*)d_in[ord[3]];
        Lin    = (const float*)d_in[ord[4]];
        Gate   = (const float*)d_in[ord[5]];
    } else {
        x      = (const float*)d_in[0];
        rscale = (const float*)d_in[1];
        Wr     = (const float*)d_in[2];
        Gate   = (const float*)d_in[3];
        Lin    = (const float*)d_in[4];
        escale = (const float*)d_in[5];
    }
    float* out = (float*)d_out;

    k0_zero<<<1, 32>>>();
    k1_router<<<LL, TPB>>>(x, rscale, Wr, escale);
    k2a_gate<<<EE * 8 * 32, 128>>>(x, Gate);
    k2b_down<<<EE * 8 * 32, 128>>>(Lin);
    k3_sum<<<(LL * DD / 4) / TPB, TPB>>>(out);
}

// round 17
// speedup vs baseline: 2.1750x; 2.1750x over previous
#include <cuda_runtime.h>
#include <cstdint>

#define DD  512    // model dim
#define EE  32     // experts
#define HH  512    // hidden per gate branch
#define LL  512    // tokens
#define TPB 256

// ---------------- scratch (static device globals; no allocs) ----------------
__device__ int            g_cnt[EE];
__device__ int            g_tok[EE][LL];
__device__ float          g_wt [EE][LL];
__device__ unsigned char  g_kis[EE][LL];
__device__ __align__(16) float g_actT[EE][HH][LL];   // [expert][h][token-slot]
__device__ __align__(16) float g_buf[2][LL * DD];

// ---------------- helpers ----------------
__device__ __forceinline__ float warp_sum(float s) {
    #pragma unroll
    for (int o = 16; o; o >>= 1) s += __shfl_xor_sync(0xffffffffu, s, o);
    return s;
}
__device__ __forceinline__ float gelu_tanh(float g) {
    float inner = 0.7978845608028654f * (g + 0.044715f * g * g * g);
    return 0.5f * g * (1.f + tanhf(inner));
}
__device__ __forceinline__ uint32_t f2tf32(float f) {
    uint32_t r;
    asm("cvt.rna.tf32.f32 %0, %1;" : "=r"(r) : "f"(f));
    return r;
}
// D(16x8,f32) += A(16x8 tf32, row) * B(8x8 tf32, col)
__device__ __forceinline__ void mma_tf32(float* c, const uint32_t* a, const uint32_t* b) {
    asm volatile(
        "mma.sync.aligned.m16n8k8.row.col.f32.tf32.tf32.f32 "
        "{%0,%1,%2,%3}, {%4,%5,%6,%7}, {%8,%9}, {%0,%1,%2,%3};"
        : "+f"(c[0]), "+f"(c[1]), "+f"(c[2]), "+f"(c[3])
        : "r"(a[0]), "r"(a[1]), "r"(a[2]), "r"(a[3]), "r"(b[0]), "r"(b[1]));
}

// ---------------- K0 ----------------
__global__ void k0_zero() {
    if (threadIdx.x < EE) g_cnt[threadIdx.x] = 0;
}

// ---------------- K1: routing (fp32 SIMT; tiny) ----------------
__global__ __launch_bounds__(TPB) void k1_router(
    const float* __restrict__ x, const float* __restrict__ router_scale,
    const float* __restrict__ Wr, const float* __restrict__ escale)
{
    const int tok = blockIdx.x, t = threadIdx.x, lane = t & 31, wid = t >> 5;

    __shared__ float srin[DD];
    __shared__ float spart[8][EE];
    __shared__ float sred[8];

    const float* xrow = x + (size_t)tok * DD;
    float v0 = xrow[t], v1 = xrow[t + TPB];
    float ss = warp_sum(v0 * v0 + v1 * v1);
    if (lane == 0) sred[wid] = ss;
    __syncthreads();
    if (t == 0) {
        float tot = 0.f;
        #pragma unroll
        for (int i = 0; i < 8; i++) tot += sred[i];
        sred[0] = rsqrtf(tot / (float)DD + 1e-6f) * rsqrtf((float)DD);
    }
    __syncthreads();
    const float scl = sred[0];
    srin[t]       = v0 * scl * router_scale[t];
    srin[t + TPB] = v1 * scl * router_scale[t + TPB];
    __syncthreads();

    {
        float acc = 0.f;
        const int d0 = wid * 64;
        #pragma unroll 8
        for (int i = 0; i < 64; i++)
            acc = fmaf(srin[d0 + i], Wr[(d0 + i) * EE + lane], acc);
        spart[wid][lane] = acc;
    }
    __syncthreads();

    if (wid == 0) {
        float l = 0.f;
        #pragma unroll
        for (int i = 0; i < 8; i++) l += spart[i][lane];

        float m1 = l; int i1 = lane;
        #pragma unroll
        for (int o = 16; o; o >>= 1) {
            float om = __shfl_xor_sync(0xffffffffu, m1, o);
            int   oi = __shfl_xor_sync(0xffffffffu, i1, o);
            if (om > m1 || (om == m1 && oi < i1)) { m1 = om; i1 = oi; }
        }
        float l2 = (lane == i1) ? -3.4e38f : l;
        float m2 = l2; int i2 = lane;
        #pragma unroll
        for (int o = 16; o; o >>= 1) {
            float om = __shfl_xor_sync(0xffffffffu, m2, o);
            int   oi = __shfl_xor_sync(0xffffffffu, i2, o);
            if (om > m2 || (om == m2 && oi < i2)) { m2 = om; i2 = oi; }
        }
        if (lane == 0) {
            float p2  = expf(m2 - m1);
            float inv = 1.f / (1.f + p2);
            float w1  = inv      * escale[i1];
            float w2  = p2 * inv * escale[i2];
            int p;
            p = atomicAdd(&g_cnt[i1], 1);
            g_tok[i1][p] = tok; g_wt[i1][p] = w1; g_kis[i1][p] = 0;
            p = atomicAdd(&g_cnt[i2], 1);
            g_tok[i2][p] = tok; g_wt[i2][p] = w2; g_kis[i2][p] = 1;
        }
    }
}

// ---------------- K2a: gate GEMM (tf32 MMA) + GeGLU ----------------
// grid = e(32) x hc(8); 256 threads (8 warps, warp tile m32 x n32)
// block output: 128 gate rows (64 G0 + 64 G1) x up-to-64 tokens; K = 512
__global__ __launch_bounds__(256) void k2a_gate(
    const float* __restrict__ x, const float* __restrict__ Gate)
{
    const int hc = blockIdx.x & 7;
    const int e  = blockIdx.x >> 3;
    const int n  = g_cnt[e];
    if (n == 0) return;

    __shared__ __align__(16) uint8_t smem_raw[128 * 68 * 4];   // 34816 B
    uint32_t (*sA)[36]  = (uint32_t(*)[36])smem_raw;           // 128 x 36 (18432 B)
    uint32_t (*sXT)[68] = (uint32_t(*)[68])(smem_raw + 18432); // 32 x 68  (8704 B)
    float    (*sC)[68]  = (float(*)[68])smem_raw;              // 128 x 68 (aliases)

    __shared__ int   stok[64];
    __shared__ float swgt[64];

    const int tid  = threadIdx.x;
    const int wid  = tid >> 5, lane = tid & 31;
    const int gid  = lane >> 2, tig = lane & 3;
    const int warp_m = wid & 3, warp_n = wid >> 2;
    const float* Gexp = Gate + (size_t)e * 2 * HH * DD;

    for (int t0 = 0; t0 < n; t0 += 64) {
        if (tid < 64) {
            bool v = (t0 + tid < n);
            stok[tid] = v ? g_tok[e][t0 + tid] : -1;
            swgt[tid] = v ? g_wt[e][t0 + tid]  : 0.f;
        }
        __syncthreads();

        float acc[2][4][4];
        #pragma unroll
        for (int mt = 0; mt < 2; mt++)
            #pragma unroll
            for (int nt = 0; nt < 4; nt++)
                #pragma unroll
                for (int q = 0; q < 4; q++) acc[mt][nt][q] = 0.f;

        for (int c = 0; c < 16; c++) {     // k-chunks of 32
            // stage A: 128 gate rows x 32 k (tf32 bits)
            #pragma unroll
            for (int r = 0; r < 4; r++) {
                int f = tid + r * 256, row = f >> 3, c4 = f & 7;
                int grow = (row < 64) ? (hc * 64 + row) : (HH + hc * 64 + row - 64);
                float4 v = *(const float4*)(Gexp + (size_t)grow * DD + c * 32 + c4 * 4);
                uint4 u = make_uint4(f2tf32(v.x), f2tf32(v.y), f2tf32(v.z), f2tf32(v.w));
                *(uint4*)&sA[row][c4 * 4] = u;
            }
            // stage XT: 32 k x 64 tok (transposed, tf32 bits)
            #pragma unroll
            for (int r = 0; r < 2; r++) {
                int f = tid + r * 256, t = f >> 3, k4 = f & 7;
                int tk = stok[t];
                float4 v = make_float4(0.f, 0.f, 0.f, 0.f);
                if (tk >= 0)
                    v = *(const float4*)(x + (size_t)tk * DD + c * 32 + k4 * 4);
                sXT[k4 * 4 + 0][t] = f2tf32(v.x);
                sXT[k4 * 4 + 1][t] = f2tf32(v.y);
                sXT[k4 * 4 + 2][t] = f2tf32(v.z);
                sXT[k4 * 4 + 3][t] = f2tf32(v.w);
            }
            __syncthreads();

            #pragma unroll
            for (int ks = 0; ks < 4; ks++) {
                uint32_t af[2][4], bf[4][2];
                #pragma unroll
                for (int mt = 0; mt < 2; mt++) {
                    int rb = warp_m * 32 + mt * 16;
                    af[mt][0] = sA[rb + gid    ][ks * 8 + tig    ];
                    af[mt][1] = sA[rb + gid + 8][ks * 8 + tig    ];
                    af[mt][2] = sA[rb + gid    ][ks * 8 + tig + 4];
                    af[mt][3] = sA[rb + gid + 8][ks * 8 + tig + 4];
                }
                #pragma unroll
                for (int nt = 0; nt < 4; nt++) {
                    int tb = warp_n * 32 + nt * 8;
                    bf[nt][0] = sXT[ks * 8 + tig    ][tb + gid];
                    bf[nt][1] = sXT[ks * 8 + tig + 4][tb + gid];
                }
                #pragma unroll
                for (int mt = 0; mt < 2; mt++)
                    #pragma unroll
                    for (int nt = 0; nt < 4; nt++)
                        mma_tf32(acc[mt][nt], af[mt], bf[nt]);
            }
            __syncthreads();
        }

        // dump C tiles to smem (aliases staging; all reads done)
        #pragma unroll
        for (int mt = 0; mt < 2; mt++) {
            int rb = warp_m * 32 + mt * 16;
            #pragma unroll
            for (int nt = 0; nt < 4; nt++) {
                int tb = warp_n * 32 + nt * 8;
                *(float2*)&sC[rb + gid    ][tb + 2 * tig] =
                    make_float2(acc[mt][nt][0], acc[mt][nt][1]);
                *(float2*)&sC[rb + gid + 8][tb + 2 * tig] =
                    make_float2(acc[mt][nt][2], acc[mt][nt][3]);
            }
        }
        __syncthreads();

        // GeGLU epilogue: rows 0..63 = G0, 64..127 = G1; store token-major f4
        #pragma unroll
        for (int r = 0; r < 4; r++) {
            int idx = tid + r * 256;          // 0..1023
            int hl = idx >> 4, tg = idx & 15;
            float o[4];
            #pragma unroll
            for (int i = 0; i < 4; i++) {
                int t = tg * 4 + i;
                float g0 = sC[hl][t], g1 = sC[64 + hl][t];
                o[i] = gelu_tanh(g0) * g1 * swgt[t];
            }
            *(float4*)&g_actT[e][hc * 64 + hl][t0 + tg * 4] =
                make_float4(o[0], o[1], o[2], o[3]);
        }
        __syncthreads();
    }
}

// ---------------- K2b: down-projection (tf32 MMA) ----------------
// grid = e(32) x dc(8); 128 threads (4 warps, warp tile m32 x n32)
// block output: 64 d x up-to-64 tokens; K = 512 (h)
__global__ __launch_bounds__(128) void k2b_down(
    const float* __restrict__ Lin)
{
    const int dc = blockIdx.x & 7;
    const int e  = blockIdx.x >> 3;
    const int n  = g_cnt[e];
    if (n == 0) return;

    __shared__ __align__(16) uint8_t smem_raw[2 * 32 * 68 * 4]; // 17408 B
    uint32_t (*sL)[68] = (uint32_t(*)[68])smem_raw;             // 32 x 68 [h][d]
    uint32_t (*sB)[68] = (uint32_t(*)[68])(smem_raw + 8704);    // 32 x 68 [h][tok]
    float    (*sC)[68] = (float(*)[68])smem_raw;                // 64 x 68 (aliases)

    __shared__ int           stok[64];
    __shared__ unsigned char skis[64];

    const int tid  = threadIdx.x;
    const int wid  = tid >> 5, lane = tid & 31;
    const int gid  = lane >> 2, tig = lane & 3;
    const int warp_m = wid & 1, warp_n = wid >> 1;
    const float* Lexp = Lin + (size_t)e * HH * DD;

    for (int t0 = 0; t0 < n; t0 += 64) {
        if (tid < 64) {
            bool v = (t0 + tid < n);
            stok[tid] = v ? g_tok[e][t0 + tid] : -1;
            skis[tid] = v ? g_kis[e][t0 + tid] : 0;
        }
        __syncthreads();

        float acc[2][4][4];
        #pragma unroll
        for (int mt = 0; mt < 2; mt++)
            #pragma unroll
            for (int nt = 0; nt < 4; nt++)
                #pragma unroll
                for (int q = 0; q < 4; q++) acc[mt][nt][q] = 0.f;

        for (int c = 0; c < 16; c++) {     // h-chunks of 32
            // stage Lin: 32 h x 64 d (natural layout; fragments read transposed)
            #pragma unroll
            for (int r = 0; r < 4; r++) {
                int f = tid + r * 128, h = f >> 4, c4 = f & 15;
                float4 v = *(const float4*)(Lexp + (size_t)(c * 32 + h) * DD + dc * 64 + c4 * 4);
                uint4 u = make_uint4(f2tf32(v.x), f2tf32(v.y), f2tf32(v.z), f2tf32(v.w));
                *(uint4*)&sL[h][c4 * 4] = u;
            }
            // stage act: 32 h x 64 tok (already token-major; no transpose)
            #pragma unroll
            for (int r = 0; r < 4; r++) {
                int f = tid + r * 128, h = f >> 4, c4 = f & 15;
                float4 v = *(const float4*)&g_actT[e][c * 32 + h][t0 + c4 * 4];
                uint4 u = make_uint4(f2tf32(v.x), f2tf32(v.y), f2tf32(v.z), f2tf32(v.w));
                *(uint4*)&sB[h][c4 * 4] = u;
            }
            __syncthreads();

            #pragma unroll
            for (int ks = 0; ks < 4; ks++) {
                uint32_t af[2][4], bf[4][2];
                #pragma unroll
                for (int mt = 0; mt < 2; mt++) {
                    int db = warp_m * 32 + mt * 16;
                    // A[m=d][k=h] = Lin[h][d] -> transposed scalar reads
                    af[mt][0] = sL[ks * 8 + tig    ][db + gid    ];
                    af[mt][1] = sL[ks * 8 + tig    ][db + gid + 8];
                    af[mt][2] = sL[ks * 8 + tig + 4][db + gid    ];
                    af[mt][3] = sL[ks * 8 + tig + 4][db + gid + 8];
                }
                #pragma unroll
                for (int nt = 0; nt < 4; nt++) {
                    int tb = warp_n * 32 + nt * 8;
                    bf[nt][0] = sB[ks * 8 + tig    ][tb + gid];
                    bf[nt][1] = sB[ks * 8 + tig + 4][tb + gid];
                }
                #pragma unroll
                for (int mt = 0; mt < 2; mt++)
                    #pragma unroll
                    for (int nt = 0; nt < 4; nt++)
                        mma_tf32(acc[mt][nt], af[mt], bf[nt]);
            }
            __syncthreads();
        }

        // dump C (rows = d 0..63, cols = tok)
        #pragma unroll
        for (int mt = 0; mt < 2; mt++) {
            int db = warp_m * 32 + mt * 16;
            #pragma unroll
            for (int nt = 0; nt < 4; nt++) {
                int tb = warp_n * 32 + nt * 8;
                *(float2*)&sC[db + gid    ][tb + 2 * tig] =
                    make_float2(acc[mt][nt][0], acc[mt][nt][1]);
                *(float2*)&sC[db + gid + 8][tb + 2 * tig] =
                    make_float2(acc[mt][nt][2], acc[mt][nt][3]);
            }
        }
        __syncthreads();

        // scatter per-token f4 (lane <-> token: conflict-free column reads)
        #pragma unroll
        for (int r = 0; r < 8; r++) {
            int idx = tid + r * 128;          // 0..1023
            int t = idx & 63, dg = idx >> 6;
            if (stok[t] >= 0) {
                float4 v = make_float4(sC[dg * 4 + 0][t], sC[dg * 4 + 1][t],
                                       sC[dg * 4 + 2][t], sC[dg * 4 + 3][t]);
                *(float4*)&g_buf[skis[t]][(size_t)stok[t] * DD + dc * 64 + dg * 4] = v;
            }
        }
        __syncthreads();
    }
}

// ---------------- K3: combine ----------------
__global__ void k3_sum(float* __restrict__ out) {
    const int i = blockIdx.x * blockDim.x + threadIdx.x;
    float4 a = ((const float4*)g_buf[0])[i];
    float4 b = ((const float4*)g_buf[1])[i];
    ((float4*)out)[i] = make_float4(a.x + b.x, a.y + b.y, a.z + b.z, a.w + b.w);
}

// ---------------- dispatch ----------------
extern "C" void kernel_launch(void* const* d_in, const int* in_sizes, int n_in,
                              void* d_out, int out_size) {
    const float *x, *rscale, *Wr, *Gate, *Lin, *escale;
    if (n_in == 6) {
        int ord[6] = {0, 1, 2, 3, 4, 5};
        for (int i = 1; i < 6; i++) {
            int v = ord[i], j = i - 1;
            while (j >= 0 && in_sizes[ord[j]] > in_sizes[v]) { ord[j + 1] = ord[j]; j--; }
            ord[j + 1] = v;
        }
        escale = (const float*)d_in[ord[0]];
        rscale = (const float*)d_in[ord[1]];
        Wr     = (const float*)d_in[ord[2]];
        x      = (const float*)d_in[ord[3]];
        Lin    = (const float*)d_in[ord[4]];
        Gate   = (const float*)d_in[ord[5]];
    } else {
        x      = (const float*)d_in[0];
        rscale = (const float*)d_in[1];
        Wr     = (const float*)d_in[2];
        Gate   = (const float*)d_in[3];
        Lin    = (const float*)d_in[4];
        escale = (const float*)d_in[5];
    }
    float* out = (float*)d_out;

    k0_zero<<<1, 32>>>();
    k1_router<<<LL, TPB>>>(x, rscale, Wr, escale);
    k2a_gate<<<EE * 8, 256>>>(x, Gate);
    k2b_down<<<EE * 8, 128>>>(Lin);
    k3_sum<<<(LL * DD / 4) / TPB, TPB>>>(out);
}